// round 4
// baseline (speedup 1.0000x reference)
#include <cuda_runtime.h>

#define NB 16
#define NT 2048
#define ND 512
#define NCH 32             // 64-t chunks (flags / pass-2 blocks)

// ---------------- scratch (device globals; no allocation allowed) ----------
__device__ __align__(16) float g_aT4[NT * NB];   // alphas, layout [t/4][b][4]
__device__ __align__(16) float g_Wt[NB * NT];    // per-step weight (cur), exact
__device__ __align__(16) float2 g_fire[NB * NT]; // per fire: (t as int bits, rem)
__device__ float g_integ0[NCH * NB];             // integ at 64-t chunk start
__device__ int   g_nf0[NCH * NB];                // fire count before chunk
__device__ int   g_nf[NB];                       // total fire count per batch
__device__ int   g_done[NB * NCH];               // chunk-ready flags (reset by pass2)

// ---------------- fused kernel: alphas (bids 1..512) + scan pass1 (bid 0) --
// Alphas block covers 64 consecutive t of one batch; warp w covers 8 t with
// rolling row registers (each hidden row loaded ONCE per d-slice: hm=hc,
// hc=hp). After stores, publishes a per-(b,chunk) flag. The scan block's 16
// threads run the reference's exact recurrence, consuming chunks as flags
// arrive, with a 32-step double buffer so L2 latency never sits on the chain.
__global__ __launch_bounds__(256)
void fused_alphas_scan(const float* __restrict__ hidden,
                       const float* __restrict__ conv_w,
                       const float* __restrict__ conv_b,
                       const float* __restrict__ lin_w,
                       const float* __restrict__ lin_b,
                       float* __restrict__ alphas,
                       float* __restrict__ token_num) {
    if (blockIdx.x == 0) {
        // ---------------- scan pass 1 (1 warp, thread b = batch) ----------
        const int b = threadIdx.x;
        if (b >= NB) return;
        const float4* ap = reinterpret_cast<const float4*>(g_aT4);
        int* flg = g_done + b * NCH;

        float integ = 0.f, tn = 0.f;
        int nf = 0;
        float4 buf[8], nbuf[8];

        while (atomicAdd(&flg[0], 0) == 0) {}
        __threadfence();
#pragma unroll
        for (int k = 0; k < 8; k++) buf[k] = __ldcg(ap + k * NB + b);

        for (int h = 0; h < 64; h++) {            // half = 32 timesteps
            if (!(h & 1)) {                        // 64-t chunk boundary snapshot
                g_integ0[(h >> 1) * NB + b] = integ;
                g_nf0[(h >> 1) * NB + b]    = nf;
            }
            const int hn = h + 1;
            if (hn < 64) {
                if (!(hn & 1)) {                   // entering next 64-t chunk
                    while (atomicAdd(&flg[hn >> 1], 0) == 0) {}
                    __threadfence();
                }
#pragma unroll
                for (int k = 0; k < 8; k++) nbuf[k] = __ldcg(ap + (hn * 8 + k) * NB + b);
            }
#pragma unroll
            for (int k = 0; k < 8; k++) {
                float a4[4] = {buf[k].x, buf[k].y, buf[k].z, buf[k].w};
#pragma unroll
                for (int i = 0; i < 4; i++) {
                    const float a   = a4[i];
                    const float s   = integ + a;       // chain: FADD
                    const bool fire = (s >= 1.0f);     // chain: FSETP (as data)
                    nf += fire ? 1 : 0;                // off-chain
                    tn += a;                           // off-chain
                    integ = fire ? (s - 1.0f) : s;     // chain: FSEL (exact -1)
                }
            }
#pragma unroll
            for (int k = 0; k < 8; k++) buf[k] = nbuf[k];
        }
        g_nf[b] = nf;
        token_num[b] = tn;
        return;
    }

    // -------------------- alphas path (512 blocks) -------------------------
    const int bid  = blockIdx.x - 1;
    const int c    = bid & (NCH - 1);       // 64-t chunk
    const int b    = bid >> 5;
    const int warp = threadIdx.x >> 5;
    const int lane = threadIdx.x & 31;
    const int t0w  = c * 64 + warp * 8;
    const float* hb = hidden + (size_t)b * NT * ND;

    float acc[8] = {0.f, 0.f, 0.f, 0.f, 0.f, 0.f, 0.f, 0.f};

#pragma unroll
    for (int j = 0; j < 4; j++) {
        const int d = lane * 4 + j * 128;
        // 12 consecutive taps for d..d+3 (3 taps each); residual folded in tap1
        const float4 c0 = *reinterpret_cast<const float4*>(&conv_w[d * 3]);
        const float4 c1 = *reinterpret_cast<const float4*>(&conv_w[d * 3 + 4]);
        const float4 c2 = *reinterpret_cast<const float4*>(&conv_w[d * 3 + 8]);
        const float4 w0 = make_float4(c0.x, c0.w, c1.z, c2.y);
        const float4 w1 = make_float4(c0.y + 1.f, c1.x + 1.f, c1.w + 1.f, c2.z + 1.f);
        const float4 w2 = make_float4(c0.z, c1.y, c2.x, c2.w);
        const float4 cb = *reinterpret_cast<const float4*>(&conv_b[d]);
        const float4 lw = *reinterpret_cast<const float4*>(&lin_w[d]);

        const float* hrow = hb + (size_t)t0w * ND + d;
        float4 hm = make_float4(0.f, 0.f, 0.f, 0.f);
        if (t0w > 0) hm = *reinterpret_cast<const float4*>(hrow - ND);
        float4 hc = *reinterpret_cast<const float4*>(hrow);

#pragma unroll
        for (int i = 0; i < 8; i++) {
            float4 hp = make_float4(0.f, 0.f, 0.f, 0.f);
            if (t0w + i + 1 < NT)
                hp = *reinterpret_cast<const float4*>(hrow + (size_t)(i + 1) * ND);

            float a = 0.f, v;
            v = fmaf(hm.x, w0.x, fmaf(hc.x, w1.x, fmaf(hp.x, w2.x, cb.x)));
            a = fmaf(fmaxf(v, 0.f), lw.x, a);
            v = fmaf(hm.y, w0.y, fmaf(hc.y, w1.y, fmaf(hp.y, w2.y, cb.y)));
            a = fmaf(fmaxf(v, 0.f), lw.y, a);
            v = fmaf(hm.z, w0.z, fmaf(hc.z, w1.z, fmaf(hp.z, w2.z, cb.z)));
            a = fmaf(fmaxf(v, 0.f), lw.z, a);
            v = fmaf(hm.w, w0.w, fmaf(hc.w, w1.w, fmaf(hp.w, w2.w, cb.w)));
            a = fmaf(fmaxf(v, 0.f), lw.w, a);
            acc[i] += a;

            hm = hc; hc = hp;
        }
    }

    const float lb = __ldg(lin_b);
    float4 av0, av1;
#pragma unroll
    for (int i = 0; i < 8; i++) {
        float a = acc[i];
#pragma unroll
        for (int o = 16; o > 0; o >>= 1) a += __shfl_xor_sync(0xffffffffu, a, o);
        const float sg = 1.0f / (1.0f + __expf(-(a + lb)));
        if (i < 4) ((float*)&av0)[i] = sg;
        else       ((float*)&av1)[i - 4] = sg;
    }
    if (lane == 0) {
        *reinterpret_cast<float4*>(&alphas[b * NT + t0w])     = av0;
        *reinterpret_cast<float4*>(&alphas[b * NT + t0w + 4]) = av1;
        const int g = t0w >> 2;
        reinterpret_cast<float4*>(g_aT4)[g * NB + b]       = av0;
        reinterpret_cast<float4*>(g_aT4)[(g + 1) * NB + b] = av1;
    }
    __syncthreads();
    if (threadIdx.x == 0) {
        __threadfence();
        atomicExch(&g_done[b * NCH + c], 1);   // publish chunk (b, c)
    }
}

// ---------------- kernel B2: parallel chunk replay (pass 2) ----------------
// One block per 64-step chunk; thread b replays from the exact boundary state
// (identical float ops in identical order => bit-exact) and does all bulk
// stores with 32-SM parallelism. Also resets the flags for the next replay.
__global__ void scan_pass2(float* __restrict__ fires) {
    const int c = blockIdx.x;
    const int b = threadIdx.x;
    if (b < NB) g_done[b * NCH + c] = 0;   // reset flags (deterministic replay)
    if (b >= NB) return;

    float integ = g_integ0[c * NB + b];
    int nf      = g_nf0[c * NB + b];
    const int tbase = c * 64;
    const float4* ap = reinterpret_cast<const float4*>(g_aT4);
    float*  fb = fires + b * NT;
    float*  wb = g_Wt + b * NT;
    float2* pb = g_fire + b * NT;

#pragma unroll
    for (int k = 0; k < 16; k++) {
        const float4 av = ap[((tbase >> 2) + k) * NB + b];
        float a4[4] = {av.x, av.y, av.z, av.w};
        float4 fout, wout;
#pragma unroll
        for (int i = 0; i < 4; i++) {
            const float a    = a4[i];
            const float dist = 1.0f - integ;
            const float s    = integ + a;
            const bool fire  = (s >= 1.0f);
            const float cur  = fire ? dist : a;
            ((float*)&fout)[i] = s;                  // pre-reset fire value
            ((float*)&wout)[i] = cur;
            const float rem = a - cur;               // exact (same op as ref)
            if (fire) pb[nf] = make_float2(__int_as_float(tbase + k * 4 + i), rem);
            nf += fire ? 1 : 0;
            integ = fire ? (s - 1.0f) : s;
        }
        const int t = tbase + k * 4;
        *reinterpret_cast<float4*>(fb + t) = fout;
        *reinterpret_cast<float4*>(wb + t) = wout;
    }
}

// ---------------- kernel C: parallel segmented gather ----------------------
// acoustic[b,r,:] = rem(prev_fire)*h[prev_fire] + sum_{t in (prev,cur]} w_t*h_t
__global__ void gather_kernel(const float* __restrict__ hidden,
                              float* __restrict__ acoustic, int ML) {
    const int r = blockIdx.x;
    const int b = blockIdx.y;
    const int d = threadIdx.x * 4;

    float4 acc = make_float4(0.f, 0.f, 0.f, 0.f);
    if (r < g_nf[b]) {
        const float* hb = hidden + (size_t)b * NT * ND + d;
        const float2 fc = g_fire[b * NT + r];
        const int end   = __float_as_int(fc.x);
        int start = 0;
        if (r > 0) {
            const float2 fp = g_fire[b * NT + r - 1];
            const int ps    = __float_as_int(fp.x);
            const float rem = fp.y;
            const float4 h  = *reinterpret_cast<const float4*>(hb + (size_t)ps * ND);
            acc.x = rem * h.x; acc.y = rem * h.y;
            acc.z = rem * h.z; acc.w = rem * h.w;
            start = ps + 1;
        }
        for (int t = start; t <= end; t++) {
            const float w  = g_Wt[b * NT + t];   // uniform broadcast load (exact cur)
            const float4 h = *reinterpret_cast<const float4*>(hb + (size_t)t * ND);
            acc.x = fmaf(w, h.x, acc.x); acc.y = fmaf(w, h.y, acc.y);
            acc.z = fmaf(w, h.z, acc.z); acc.w = fmaf(w, h.w, acc.w);
        }
    }
    // r >= nf -> zeros (reference zero-pads); also overwrites 0xAA poison.
    *reinterpret_cast<float4*>(&acoustic[((size_t)b * ML + r) * ND + d]) = acc;
}

// ---------------- launch ----------------------------------------------------
extern "C" void kernel_launch(void* const* d_in, const int* in_sizes, int n_in,
                              void* d_out, int out_size) {
    const float* hidden = (const float*)d_in[0];
    const float* conv_w = (const float*)d_in[1];
    const float* conv_b = (const float*)d_in[2];
    const float* lin_w  = (const float*)d_in[3];
    const float* lin_b  = (const float*)d_in[4];
    float* out = (float*)d_out;

    // out = concat(acoustic[B,ML,D], token_num[B], alphas[B,T], fires[B,T])
    const int ML = (out_size - NB - 2 * NB * NT) / (NB * ND);
    float* acoustic  = out;
    float* token_num = out + (size_t)NB * ML * ND;
    float* alphas    = token_num + NB;
    float* fires     = alphas + NB * NT;

    fused_alphas_scan<<<1 + NCH * NB, 256>>>(hidden, conv_w, conv_b, lin_w, lin_b,
                                             alphas, token_num);
    scan_pass2<<<NCH, 32>>>(fires);
    if (ML > 0) gather_kernel<<<dim3(ML, NB), ND / 4>>>(hidden, acoustic, ML);
}

// round 5
// speedup vs baseline: 1.4334x; 1.4334x over previous
#include <cuda_runtime.h>

#define NB 16
#define NT 2048
#define ND 512
#define TBLK 16            // timesteps per alphas block
#define CH 32              // pass-2 chunk length (timesteps)
#define NCH (NT / CH)      // 64 chunks

// ---------------- scratch (device globals; no allocation allowed) ----------
__device__ __align__(16) float g_aT4[NT * NB];   // alphas, layout [t/4][b][4]
__device__ __align__(16) float g_Wt[NB * NT];    // per-step weight (cur), exact
__device__ __align__(16) float2 g_fire[NB * NT]; // per fire: (t as int bits, rem)
__device__ float g_integ0[NCH * NB];             // integ at chunk start
__device__ int   g_nf0[NCH * NB];                // fire count before chunk
__device__ int   g_nf[NB];                       // total fire count per batch

// ---------------- kernel A: alphas via smem tile ----------------------------
// Block = 256 threads covers 16 consecutive t of one batch. Cooperative load
// of rows t0-1..t0+16 (18 rows, 36KB smem) with 9 independent LDG.128/thread
// (high MLP), then 3-tap conv + GEMV read from smem (each hidden row fetched
// from DRAM exactly once per block => 1.125x traffic). Warp w covers t pair
// (2w, 2w+1); lane covers d = 4*lane + 128*j.
__global__ __launch_bounds__(256, 6)
void alphas_kernel(const float* __restrict__ hidden,
                   const float* __restrict__ conv_w,
                   const float* __restrict__ conv_b,
                   const float* __restrict__ lin_w,
                   const float* __restrict__ lin_b,
                   float* __restrict__ alphas) {
    __shared__ float sh[(TBLK + 2) * ND];   // 18 * 512 * 4B = 36KB

    const int b  = blockIdx.y;
    const int t0 = blockIdx.x * TBLK;

    // cooperative load: rows t0-1 .. t0+16 (zeros outside [0,NT))
    {
        const float4* hb = reinterpret_cast<const float4*>(
            hidden + (size_t)b * NT * ND);
#pragma unroll
        for (int it = 0; it < (TBLK + 2) * (ND / 4) / 256; it++) {
            const int idx = it * 256 + threadIdx.x;       // 0 .. 2303
            const int row = idx >> 7;                     // 0..17
            const int q   = idx & 127;                    // float4 within row
            const int t   = t0 + row - 1;
            float4 v = make_float4(0.f, 0.f, 0.f, 0.f);
            if (t >= 0 && t < NT) v = hb[(size_t)t * (ND / 4) + q];
            *reinterpret_cast<float4*>(&sh[row * ND + q * 4]) = v;
        }
    }
    __syncthreads();

    const int warp = threadIdx.x >> 5;
    const int lane = threadIdx.x & 31;
    const int tl   = warp * 2;              // local t (0..14), rows tl..tl+3

    float acc0 = 0.f, acc1 = 0.f;

#pragma unroll 1
    for (int j = 0; j < 4; j++) {
        const int d = lane * 4 + j * 128;
        // 12 consecutive taps for d..d+3 (3 taps each); residual folded in tap1
        const float4 c0 = *reinterpret_cast<const float4*>(&conv_w[d * 3]);
        const float4 c1 = *reinterpret_cast<const float4*>(&conv_w[d * 3 + 4]);
        const float4 c2 = *reinterpret_cast<const float4*>(&conv_w[d * 3 + 8]);
        const float4 w0 = make_float4(c0.x, c0.w, c1.z, c2.y);
        const float4 w1 = make_float4(c0.y + 1.f, c1.x + 1.f, c1.w + 1.f, c2.z + 1.f);
        const float4 w2 = make_float4(c0.z, c1.y, c2.x, c2.w);
        const float4 cb = *reinterpret_cast<const float4*>(&conv_b[d]);
        const float4 lw = *reinterpret_cast<const float4*>(&lin_w[d]);

        const float4 r0 = *reinterpret_cast<const float4*>(&sh[(tl + 0) * ND + d]);
        const float4 r1 = *reinterpret_cast<const float4*>(&sh[(tl + 1) * ND + d]);
        const float4 r2 = *reinterpret_cast<const float4*>(&sh[(tl + 2) * ND + d]);
        const float4 r3 = *reinterpret_cast<const float4*>(&sh[(tl + 3) * ND + d]);

        float v;
        // t = t0+tl   : hm=r0, hc=r1, hp=r2
        v = fmaf(r0.x, w0.x, fmaf(r1.x, w1.x, fmaf(r2.x, w2.x, cb.x)));
        acc0 = fmaf(fmaxf(v, 0.f), lw.x, acc0);
        v = fmaf(r0.y, w0.y, fmaf(r1.y, w1.y, fmaf(r2.y, w2.y, cb.y)));
        acc0 = fmaf(fmaxf(v, 0.f), lw.y, acc0);
        v = fmaf(r0.z, w0.z, fmaf(r1.z, w1.z, fmaf(r2.z, w2.z, cb.z)));
        acc0 = fmaf(fmaxf(v, 0.f), lw.z, acc0);
        v = fmaf(r0.w, w0.w, fmaf(r1.w, w1.w, fmaf(r2.w, w2.w, cb.w)));
        acc0 = fmaf(fmaxf(v, 0.f), lw.w, acc0);
        // t = t0+tl+1 : hm=r1, hc=r2, hp=r3
        v = fmaf(r1.x, w0.x, fmaf(r2.x, w1.x, fmaf(r3.x, w2.x, cb.x)));
        acc1 = fmaf(fmaxf(v, 0.f), lw.x, acc1);
        v = fmaf(r1.y, w0.y, fmaf(r2.y, w1.y, fmaf(r3.y, w2.y, cb.y)));
        acc1 = fmaf(fmaxf(v, 0.f), lw.y, acc1);
        v = fmaf(r1.z, w0.z, fmaf(r2.z, w1.z, fmaf(r3.z, w2.z, cb.z)));
        acc1 = fmaf(fmaxf(v, 0.f), lw.z, acc1);
        v = fmaf(r1.w, w0.w, fmaf(r2.w, w1.w, fmaf(r3.w, w2.w, cb.w)));
        acc1 = fmaf(fmaxf(v, 0.f), lw.w, acc1);
    }

#pragma unroll
    for (int o = 16; o > 0; o >>= 1) {
        acc0 += __shfl_xor_sync(0xffffffffu, acc0, o);
        acc1 += __shfl_xor_sync(0xffffffffu, acc1, o);
    }
    if (lane == 0) {
        const float lb = __ldg(lin_b);
        const int t = t0 + tl;
        const float2 av = make_float2(1.0f / (1.0f + __expf(-(acc0 + lb))),
                                      1.0f / (1.0f + __expf(-(acc1 + lb))));
        *reinterpret_cast<float2*>(&alphas[b * NT + t]) = av;
        // g_aT4 layout [t/4][b][4]; t is even so float2 store is 8B-aligned
        *reinterpret_cast<float2*>(&g_aT4[((t >> 2) * NB + b) * 4 + (t & 3)]) = av;
    }
}

// ---------------- kernel B1: minimal sequential chain (pass 1) -------------
// One warp; thread b runs the reference's exact recurrence with ONLY the
// integ/nf/tn state. Double-buffered 32-step register tiles keep load latency
// off the 12-cyc/step chain. Snapshots (integ, nf) every CH steps for pass 2.
__global__ void scan_pass1(float* __restrict__ token_num) {
    const int b = threadIdx.x;
    if (b >= NB) return;

    const float4* ap = reinterpret_cast<const float4*>(g_aT4) + b;
    float4 buf_cur[8], buf_nxt[8];
#pragma unroll
    for (int k = 0; k < 8; k++) buf_cur[k] = ap[k * NB];

    float integ = 0.f, tn = 0.f;
    int nf = 0;

    for (int t0 = 0; t0 < NT; t0 += CH) {
        g_integ0[(t0 >> 5) * NB + b] = integ;   // chunk-boundary snapshot
        g_nf0[(t0 >> 5) * NB + b]   = nf;
        if (t0 + CH < NT) {
#pragma unroll
            for (int k = 0; k < 8; k++) buf_nxt[k] = ap[((t0 >> 2) + 8 + k) * NB];
        }
#pragma unroll
        for (int k = 0; k < 8; k++) {
            float a4[4] = {buf_cur[k].x, buf_cur[k].y, buf_cur[k].z, buf_cur[k].w};
#pragma unroll
            for (int i = 0; i < 4; i++) {
                const float a   = a4[i];
                const float s   = integ + a;          // chain: FADD
                const bool fire = (s >= 1.0f);        // chain: FSETP (as data)
                nf += fire ? 1 : 0;                   // off-chain
                tn += a;                              // off-chain
                integ = fire ? (s - 1.0f) : s;        // chain: FSEL (exact -1)
            }
        }
#pragma unroll
        for (int k = 0; k < 8; k++) buf_cur[k] = buf_nxt[k];
    }
    g_nf[b] = nf;
    token_num[b] = tn;
}

// ---------------- kernel B2: parallel chunk replay (pass 2) ----------------
// One block per 32-step chunk; thread b replays from the exact boundary state
// (identical float ops in identical order => bit-exact) and does all bulk
// stores with 64-SM parallelism.
__global__ void scan_pass2(float* __restrict__ fires) {
    const int c = blockIdx.x;
    const int b = threadIdx.x;
    if (b >= NB) return;

    float integ = g_integ0[c * NB + b];
    int nf      = g_nf0[c * NB + b];
    const int tbase = c * CH;
    const float4* ap = reinterpret_cast<const float4*>(g_aT4) + b;
    float*  fb = fires + b * NT;
    float*  wb = g_Wt + b * NT;
    float2* pb = g_fire + b * NT;

#pragma unroll
    for (int k = 0; k < 8; k++) {
        const float4 av = ap[((tbase >> 2) + k) * NB];
        float a4[4] = {av.x, av.y, av.z, av.w};
        float4 fout, wout;
#pragma unroll
        for (int i = 0; i < 4; i++) {
            const float a    = a4[i];
            const float dist = 1.0f - integ;
            const float s    = integ + a;
            const bool fire  = (s >= 1.0f);
            const float cur  = fire ? dist : a;
            ((float*)&fout)[i] = s;                  // pre-reset fire value
            ((float*)&wout)[i] = cur;
            const float rem = a - cur;               // exact (same op as ref)
            if (fire) pb[nf] = make_float2(__int_as_float(tbase + k * 4 + i), rem);
            nf += fire ? 1 : 0;
            integ = fire ? (s - 1.0f) : s;
        }
        const int t = tbase + k * 4;
        *reinterpret_cast<float4*>(fb + t) = fout;
        *reinterpret_cast<float4*>(wb + t) = wout;
    }
}

// ---------------- kernel C: parallel segmented gather ----------------------
// acoustic[b,r,:] = rem(prev_fire)*h[prev_fire] + sum_{t in (prev,cur]} w_t*h_t
__global__ void gather_kernel(const float* __restrict__ hidden,
                              float* __restrict__ acoustic, int ML) {
    const int r = blockIdx.x;
    const int b = blockIdx.y;
    const int d = threadIdx.x * 4;

    float4 acc = make_float4(0.f, 0.f, 0.f, 0.f);
    if (r < g_nf[b]) {
        const float* hb = hidden + (size_t)b * NT * ND + d;
        const float2 fc = g_fire[b * NT + r];
        const int end   = __float_as_int(fc.x);
        int start = 0;
        if (r > 0) {
            const float2 fp = g_fire[b * NT + r - 1];
            const int ps    = __float_as_int(fp.x);
            const float rem = fp.y;
            const float4 h  = *reinterpret_cast<const float4*>(hb + (size_t)ps * ND);
            acc.x = rem * h.x; acc.y = rem * h.y;
            acc.z = rem * h.z; acc.w = rem * h.w;
            start = ps + 1;
        }
        for (int t = start; t <= end; t++) {
            const float w  = g_Wt[b * NT + t];   // uniform broadcast load (exact cur)
            const float4 h = *reinterpret_cast<const float4*>(hb + (size_t)t * ND);
            acc.x = fmaf(w, h.x, acc.x); acc.y = fmaf(w, h.y, acc.y);
            acc.z = fmaf(w, h.z, acc.z); acc.w = fmaf(w, h.w, acc.w);
        }
    }
    // r >= nf -> zeros (reference zero-pads); also overwrites 0xAA poison.
    *reinterpret_cast<float4*>(&acoustic[((size_t)b * ML + r) * ND + d]) = acc;
}

// ---------------- launch ----------------------------------------------------
extern "C" void kernel_launch(void* const* d_in, const int* in_sizes, int n_in,
                              void* d_out, int out_size) {
    const float* hidden = (const float*)d_in[0];
    const float* conv_w = (const float*)d_in[1];
    const float* conv_b = (const float*)d_in[2];
    const float* lin_w  = (const float*)d_in[3];
    const float* lin_b  = (const float*)d_in[4];
    float* out = (float*)d_out;

    // out = concat(acoustic[B,ML,D], token_num[B], alphas[B,T], fires[B,T])
    const int ML = (out_size - NB - 2 * NB * NT) / (NB * ND);
    float* acoustic  = out;
    float* token_num = out + (size_t)NB * ML * ND;
    float* alphas    = token_num + NB;
    float* fires     = alphas + NB * NT;

    alphas_kernel<<<dim3(NT / TBLK, NB), 256>>>(hidden, conv_w, conv_b,
                                                lin_w, lin_b, alphas);
    scan_pass1<<<1, 32>>>(token_num);
    scan_pass2<<<NCH, 32>>>(fires);
    if (ML > 0) gather_kernel<<<dim3(ML, NB), ND / 4>>>(hidden, acoustic, ML);
}